// round 2
// baseline (speedup 1.0000x reference)
#include <cuda_runtime.h>
#include <math.h>

#define BSZ   8
#define SEQL  8192
#define CHN   256
#define ORD   64
#define NFFT  1024
#define HOP   512
#define NCHUNK 16
#define MTOT  (BSZ*SEQL)          // 65536
#define NELEM (BSZ*SEQL*CHN)      // 16777216

// ---------------- device scratch (no allocations allowed) ----------------
__device__ float  g_xeT[NELEM];       // [b][c][t]  transposed encode output
__device__ float  g_y1T[NELEM];       // [b][c][t]  gelu(conv) output
__device__ float  g_y2[NELEM];        // [b][t][c]  fc output (LN in-place)
__device__ float2 g_Kf[CHN*NFFT];     // per-channel 1024-pt spectrum of B/A
__device__ float2 g_tw[NFFT];         // twiddles e^{-2pi i j / 1024}
__device__ float  g_mx_xe[BSZ*CHN];
__device__ unsigned int g_mx_y[BSZ*CHN];

__device__ __forceinline__ float2 cmulf(float2 a, float2 b){
    return make_float2(fmaf(a.x,b.x,-a.y*b.y), fmaf(a.x,b.y,a.y*b.x));
}
__device__ __forceinline__ float gelu_exact(float v){
    return 0.5f*v*(1.0f+erff(v*0.70710678118654752f));
}

// ---------------- init: zero maxima + twiddle table ----------------
__global__ void init_kernel(){
    int i = blockIdx.x*blockDim.x + threadIdx.x;
    if (i < BSZ*CHN) g_mx_y[i] = 0u;
    if (i < NFFT){
        float th = -6.283185307179586f * (float)i / (float)NFFT;
        float s,c; sincosf(th,&s,&c);
        g_tw[i] = make_float2(c, s);
    }
}

// ---------------- kernel spectrum: Kf[c][k] = B(w_k)/A(w_k), w_k = e^{-2pi i k/1024}
__global__ void kf_kernel(const float* __restrict__ A, const float* __restrict__ Bp){
    int idx = blockIdx.x*blockDim.x + threadIdx.x;
    if (idx >= CHN*NFFT) return;
    int c = idx >> 10, k = idx & (NFFT-1);
    float th = -6.283185307179586f * (float)k / (float)NFFT;
    float sw, cw; sincosf(th, &sw, &cw);
    float wr = 1.f, wi = 0.f;
    float nr = 0.f, ni = 0.f, dr = 1.f, di = 0.f;
    const float* Ac = A  + c*ORD;
    const float* Bc = Bp + c*ORD;
    #pragma unroll 8
    for (int n = 0; n < ORD; n++){
        float bn = Bc[n];
        nr = fmaf(bn, wr, nr); ni = fmaf(bn, wi, ni);
        float wr2 = wr*cw - wi*sw;            // advance to w^{n+1}
        float wi2 = wr*sw + wi*cw;
        wr = wr2; wi = wi2;
        float an = Ac[n];                      // denominator: 1 + sum A[n] w^{n+1}
        dr = fmaf(an, wr, dr); di = fmaf(an, wi, di);
    }
    float inv = 1.f/(dr*dr + di*di);
    g_Kf[idx] = make_float2((nr*dr + ni*di)*inv, (ni*dr - nr*di)*inv);
}

// ---------------- generic fp32 GEMM: C[m,n] = sum_k A[m,k]*W[n,k] + epilogue ----
// MODEA: 0 -> A row-major (lda=CHN); 1 -> A in transposed [b][k][t] layout
// EPI:   0 -> bias, write transposed out[b][n][t]
//        1 -> gelu(acc+bias) + skipT, write normal out[m*CHN+n]
//        2 -> acc+bias, write normal out[m*CHN+n]
template<int MODEA, int EPI>
__global__ __launch_bounds__(256)
void gemm_kernel(const float* __restrict__ A, const float* __restrict__ Bw,
                 const float* __restrict__ bias, const float* __restrict__ skipT,
                 float* __restrict__ out)
{
    __shared__ __align__(16) float As[16][128];
    __shared__ __align__(16) float Bs[16][128];
    const int m0 = blockIdx.x * 128;
    const int n0 = blockIdx.y * 128;
    const int tid = threadIdx.x;
    const int tx = tid & 15, ty = tid >> 4;
    const int bb = m0 >> 13;
    const int t0 = m0 & (SEQL-1);
    const int bbase = bb * (CHN*SEQL);

    float acc[64];
    #pragma unroll
    for (int i=0;i<64;i++) acc[i]=0.f;

    for (int k0 = 0; k0 < CHN; k0 += 16){
        #pragma unroll
        for (int l=0;l<2;l++){
            int f = tid + l*256;
            if (MODEA == 0){
                int row = f >> 2, kc = (f & 3) << 2;
                float4 v = *(const float4*)(A + (m0+row)*CHN + k0 + kc);
                As[kc+0][row]=v.x; As[kc+1][row]=v.y; As[kc+2][row]=v.z; As[kc+3][row]=v.w;
            } else {
                int kk = f >> 5, mc = (f & 31) << 2;
                float4 v = *(const float4*)(A + bbase + (k0+kk)*SEQL + t0 + mc);
                *(float4*)&As[kk][mc] = v;
            }
            int row = f >> 2, kc = (f & 3) << 2;
            float4 v = *(const float4*)(Bw + (n0+row)*CHN + k0 + kc);
            Bs[kc+0][row]=v.x; Bs[kc+1][row]=v.y; Bs[kc+2][row]=v.z; Bs[kc+3][row]=v.w;
        }
        __syncthreads();
        #pragma unroll
        for (int kk=0; kk<16; kk++){
            float4 a0 = *(const float4*)&As[kk][ty*8];
            float4 a1 = *(const float4*)&As[kk][ty*8+4];
            float4 b0 = *(const float4*)&Bs[kk][tx*8];
            float4 b1 = *(const float4*)&Bs[kk][tx*8+4];
            float av[8] = {a0.x,a0.y,a0.z,a0.w,a1.x,a1.y,a1.z,a1.w};
            float bv[8] = {b0.x,b0.y,b0.z,b0.w,b1.x,b1.y,b1.z,b1.w};
            #pragma unroll
            for (int i=0;i<8;i++)
                #pragma unroll
                for (int j=0;j<8;j++)
                    acc[i*8+j] = fmaf(av[i], bv[j], acc[i*8+j]);
        }
        __syncthreads();
    }

    float bv[8];
    #pragma unroll
    for (int j=0;j<8;j++) bv[j] = bias[n0 + tx*8 + j];

    if (EPI == 0){
        #pragma unroll
        for (int j=0;j<8;j++){
            int base = bbase + (n0 + tx*8 + j)*SEQL + t0 + ty*8;
            float4 p0 = make_float4(acc[0*8+j]+bv[j], acc[1*8+j]+bv[j],
                                    acc[2*8+j]+bv[j], acc[3*8+j]+bv[j]);
            float4 p1 = make_float4(acc[4*8+j]+bv[j], acc[5*8+j]+bv[j],
                                    acc[6*8+j]+bv[j], acc[7*8+j]+bv[j]);
            *(float4*)(out + base)     = p0;
            *(float4*)(out + base + 4) = p1;
        }
    } else {
        if (EPI == 1){
            #pragma unroll
            for (int j=0;j<8;j++){
                int base = bbase + (n0 + tx*8 + j)*SEQL + t0 + ty*8;
                float4 s0 = *(const float4*)(skipT + base);
                float4 s1 = *(const float4*)(skipT + base + 4);
                float sk[8] = {s0.x,s0.y,s0.z,s0.w,s1.x,s1.y,s1.z,s1.w};
                #pragma unroll
                for (int i=0;i<8;i++)
                    acc[i*8+j] = gelu_exact(acc[i*8+j] + bv[j]) + sk[i];
            }
        } else {
            #pragma unroll
            for (int i=0;i<8;i++)
                #pragma unroll
                for (int j=0;j<8;j++)
                    acc[i*8+j] += bv[j];
        }
        #pragma unroll
        for (int i=0;i<8;i++){
            int base = (m0 + ty*8 + i)*CHN + n0 + tx*8;
            *(float4*)(out + base)     = make_float4(acc[i*8+0],acc[i*8+1],acc[i*8+2],acc[i*8+3]);
            *(float4*)(out + base + 4) = make_float4(acc[i*8+4],acc[i*8+5],acc[i*8+6],acc[i*8+7]);
        }
    }
}

// ---------------- radix-4 Stockham FFT, N=1024, 256 threads, result ends in sb1
__device__ __forceinline__ void fft1024(float2* sb0, float2* sb1, const float2* stw, int tid){
    #pragma unroll
    for (int st=0; st<5; st++){
        const int s = 1 << (2*st);
        float2* src = (st & 1) ? sb1 : sb0;
        float2* dst = (st & 1) ? sb0 : sb1;
        int ps = tid & ~(s-1);         // p*s
        float2 a = src[tid];
        float2 b = src[tid+256];
        float2 c = src[tid+512];
        float2 d = src[tid+768];
        float2 w1 = stw[ps];
        float2 w2 = stw[(2*ps) & (NFFT-1)];
        float2 w3 = stw[(3*ps) & (NFFT-1)];
        float2 apc = make_float2(a.x+c.x, a.y+c.y);
        float2 amc = make_float2(a.x-c.x, a.y-c.y);
        float2 bpd = make_float2(b.x+d.x, b.y+d.y);
        float2 bmd = make_float2(b.x-d.x, b.y-d.y);
        float2 jb  = make_float2(-bmd.y, bmd.x);
        int j0 = tid + 3*ps;
        dst[j0]       = make_float2(apc.x+bpd.x, apc.y+bpd.y);
        dst[j0+s]     = cmulf(w1, make_float2(amc.x-jb.x, amc.y-jb.y));
        dst[j0+2*s]   = cmulf(w2, make_float2(apc.x-bpd.x, apc.y-bpd.y));
        dst[j0+3*s]   = cmulf(w3, make_float2(amc.x+jb.x, amc.y+jb.y));
        __syncthreads();
    }
}

// ---------------- overlap-save FFT conv, 2 channels packed per complex FFT ----
// grid: (NCHUNK=16, CHN/2=128, BSZ=8), 256 threads
__global__ __launch_bounds__(256)
void fftconv_kernel(const float* __restrict__ h0){
    __shared__ __align__(16) float2 sb0[NFFT];
    __shared__ __align__(16) float2 sb1[NFFT];
    __shared__ __align__(16) float2 stw[NFFT];
    __shared__ __align__(16) float2 skeep[HOP];
    const int chunk = blockIdx.x;
    const int cp    = blockIdx.y;
    const int b     = blockIdx.z;
    const int tid   = threadIdx.x;
    const int rowA  = (b*CHN + 2*cp) * SEQL;
    const int rowB  = rowA + SEQL;
    const int g0    = chunk*HOP - HOP;

    #pragma unroll
    for (int l=0;l<4;l++){
        int i = tid + l*256;
        stw[i] = g_tw[i];
        int t = g0 + i;
        float xa = 0.f, xb = 0.f;
        if (t >= 0){ xa = g_xeT[rowA + t]; xb = g_xeT[rowB + t]; }
        sb0[i] = make_float2(xa, xb);
        if (i >= HOP) skeep[i-HOP] = make_float2(xa, xb);
    }
    __syncthreads();

    fft1024(sb0, sb1, stw, tid);        // forward; result in sb1

    const int cbase0 = (2*cp)*NFFT;
    const int cbase1 = cbase0 + NFFT;
    #pragma unroll
    for (int l=0;l<4;l++){
        int k = tid + l*256;
        float2 Z  = sb1[k];
        float2 Zr = sb1[(NFFT - k) & (NFFT-1)];
        float2 Xa = make_float2(0.5f*(Z.x+Zr.x),  0.5f*(Z.y-Zr.y));
        float2 Xb = make_float2(0.5f*(Z.y+Zr.y), -0.5f*(Z.x-Zr.x));
        float2 Ka = g_Kf[cbase0 + k];
        float2 Kb = g_Kf[cbase1 + k];
        float2 Ya = cmulf(Xa, Ka);
        float2 Yb = cmulf(Xb, Kb);
        // W = Ya + i*Yb ; store conj(W) for inverse-via-conjugate
        sb0[k] = make_float2(Ya.x - Yb.y, -(Ya.y + Yb.x));
    }
    __syncthreads();

    fft1024(sb0, sb1, stw, tid);        // "inverse"; actual = conj(sb1)/N

    const float h0v = h0[0];
    const float invN = 1.0f/(float)NFFT;
    #pragma unroll
    for (int l=0;l<2;l++){
        int i = HOP + tid + l*256;
        int t = g0 + i;                 // global time in [chunk*HOP, chunk*HOP+HOP)
        float ha =  sb1[i].x * invN;
        float hb = -sb1[i].y * invN;
        float2 xv = skeep[i-HOP];
        g_y1T[rowA + t] = gelu_exact(ha + h0v*xv.x);
        g_y1T[rowB + t] = gelu_exact(hb + h0v*xv.y);
    }
}

// ---------------- LayerNorm over channels, in-place on g_y2; warp per row ----
__global__ __launch_bounds__(256)
void ln_kernel(const float* __restrict__ gamma, const float* __restrict__ beta){
    int warp = threadIdx.x >> 5, lane = threadIdx.x & 31;
    int row = blockIdx.x*8 + warp;
    float* p = g_y2 + row*CHN + lane*8;
    float4 v0 = *(float4*)p;
    float4 v1 = *(float4*)(p+4);
    float s  = v0.x+v0.y+v0.z+v0.w + v1.x+v1.y+v1.z+v1.w;
    float ss = v0.x*v0.x+v0.y*v0.y+v0.z*v0.z+v0.w*v0.w
             + v1.x*v1.x+v1.y*v1.y+v1.z*v1.z+v1.w*v1.w;
    #pragma unroll
    for (int o=16;o>0;o>>=1){
        s  += __shfl_xor_sync(0xffffffffu, s,  o);
        ss += __shfl_xor_sync(0xffffffffu, ss, o);
    }
    float mu  = s * (1.f/CHN);
    float var = ss * (1.f/CHN) - mu*mu;
    float r = rsqrtf(var + 1e-5f);
    float4 g0 = *(const float4*)(gamma + lane*8);
    float4 g1 = *(const float4*)(gamma + lane*8 + 4);
    float4 be0 = *(const float4*)(beta + lane*8);
    float4 be1 = *(const float4*)(beta + lane*8 + 4);
    v0.x = (v0.x-mu)*r*g0.x + be0.x;  v0.y = (v0.y-mu)*r*g0.y + be0.y;
    v0.z = (v0.z-mu)*r*g0.z + be0.z;  v0.w = (v0.w-mu)*r*g0.w + be0.w;
    v1.x = (v1.x-mu)*r*g1.x + be1.x;  v1.y = (v1.y-mu)*r*g1.y + be1.y;
    v1.z = (v1.z-mu)*r*g1.z + be1.z;  v1.w = (v1.w-mu)*r*g1.w + be1.w;
    *(float4*)p     = v0;
    *(float4*)(p+4) = v1;
}

// ---------------- max|xe| per (b,c) row of xeT ----------------
__global__ __launch_bounds__(256)
void mxxe_kernel(){
    int base = blockIdx.x * SEQL;
    float m = 0.f;
    for (int j = threadIdx.x*4; j < SEQL; j += 1024){
        float4 v = *(const float4*)(g_xeT + base + j);
        m = fmaxf(m, fmaxf(fmaxf(fabsf(v.x),fabsf(v.y)),fmaxf(fabsf(v.z),fabsf(v.w))));
    }
    __shared__ float sm[256];
    sm[threadIdx.x] = m; __syncthreads();
    for (int o=128;o>0;o>>=1){
        if (threadIdx.x<o) sm[threadIdx.x]=fmaxf(sm[threadIdx.x], sm[threadIdx.x+o]);
        __syncthreads();
    }
    if (threadIdx.x==0) g_mx_xe[blockIdx.x] = sm[0];
}

// ---------------- max|y| per (b,c) via bitwise atomicMax ----------------
__global__ __launch_bounds__(256)
void mxy_kernel(const float* __restrict__ y){
    int b   = blockIdx.x >> 5;
    int seg = blockIdx.x & 31;
    int c   = threadIdx.x;
    float m = 0.f;
    int base = (b*SEQL + seg*256)*CHN + c;
    for (int t=0;t<256;t++) m = fmaxf(m, fabsf(y[base + t*CHN]));
    atomicMax(&g_mx_y[b*CHN + c], __float_as_uint(m));
}

__global__ void hfinal_kernel(float* __restrict__ out){
    int i = blockIdx.x*blockDim.x + threadIdx.x;
    if (i < BSZ*CHN)
        out[i] = __uint_as_float(g_mx_y[i]) / (g_mx_xe[i] + 1e-6f);
}

// ---------------- launch ----------------
extern "C" void kernel_launch(void* const* d_in, const int* in_sizes, int n_in,
                              void* d_out, int out_size) {
    const float* x     = (const float*)d_in[0];
    const float* A     = (const float*)d_in[1];
    const float* Bp    = (const float*)d_in[2];
    const float* h0    = (const float*)d_in[3];
    const float* W_enc = (const float*)d_in[4];
    const float* b_enc = (const float*)d_in[5];
    const float* W_fc  = (const float*)d_in[6];
    const float* b_fc  = (const float*)d_in[7];
    const float* gamma = (const float*)d_in[8];
    const float* beta  = (const float*)d_in[9];
    const float* W_dec = (const float*)d_in[10];
    const float* b_dec = (const float*)d_in[11];
    float* out = (float*)d_out;

    float *p_xeT, *p_y1T, *p_y2;
    cudaGetSymbolAddress((void**)&p_xeT, g_xeT);
    cudaGetSymbolAddress((void**)&p_y1T, g_y1T);
    cudaGetSymbolAddress((void**)&p_y2,  g_y2);

    init_kernel<<<8, 256>>>();
    kf_kernel<<<(CHN*NFFT)/256, 256>>>(A, Bp);

    dim3 gg(MTOT/128, CHN/128);
    // encode: xeT = (x @ W_enc^T + b_enc), transposed layout
    gemm_kernel<0,0><<<gg, 256>>>(x, W_enc, b_enc, nullptr, p_xeT);
    mxxe_kernel<<<BSZ*CHN, 256>>>();
    // FFT long conv + gelu -> y1T
    fftconv_kernel<<<dim3(NCHUNK, CHN/2, BSZ), 256>>>(h0);
    // fc: y2 = gelu(y1 @ W_fc^T + b_fc) + xe, normal layout
    gemm_kernel<1,1><<<gg, 256>>>(p_y1T, W_fc, b_fc, p_xeT, p_y2);
    // LayerNorm in-place
    ln_kernel<<<MTOT/8, 256>>>(gamma, beta);
    // decode: y = y2n @ W_dec^T + b_dec -> d_out
    gemm_kernel<0,2><<<gg, 256>>>(p_y2, W_dec, b_dec, nullptr, out);
    // h = max|y| / (max|xe| + eps)
    mxy_kernel<<<BSZ*32, 256>>>(out);
    hfinal_kernel<<<8, 256>>>(out + NELEM);
}

// round 7
// speedup vs baseline: 1.5484x; 1.5484x over previous
#include <cuda_runtime.h>
#include <cuda_bf16.h>
#include <math.h>
#include <stdint.h>

#define BSZ   8
#define SEQL  8192
#define CHN   256
#define ORD   64
#define NFFT  1024
#define HOP   512
#define NCHUNK 16
#define MTOT  (BSZ*SEQL)          // 65536
#define NELEM (BSZ*SEQL*CHN)      // 16777216

// ---------------- device scratch ----------------
__device__ float  g_xeT[NELEM];       // [b][c][t]
__device__ float  g_y1T[NELEM];       // [b][c][t]
__device__ float  g_y2[NELEM];        // [b][t][c]
__device__ float2 g_Kf[CHN*NFFT];
__device__ float2 g_tw[NFFT];
__device__ float  g_mx_xe[BSZ*CHN];
__device__ unsigned int g_mx_y[BSZ*CHN];

__device__ __forceinline__ float2 cmulf(float2 a, float2 b){
    return make_float2(fmaf(a.x,b.x,-a.y*b.y), fmaf(a.x,b.y,a.y*b.x));
}
__device__ __forceinline__ float gelu_exact(float v){
    return 0.5f*v*(1.0f+erff(v*0.70710678118654752f));
}
__device__ __forceinline__ uint32_t smem_to_u32(const void* p){
    uint32_t a;
    asm("{ .reg .u64 t; cvta.to.shared.u64 t, %1; cvt.u32.u64 %0, t; }" : "=r"(a) : "l"(p));
    return a;
}

// bf16 hi/lo split packer: returns hi-pair, writes lo-pair
__device__ __forceinline__ unsigned pk(float f0, float f1, unsigned &lo){
    __nv_bfloat16 h0 = __float2bfloat16_rn(f0);
    __nv_bfloat16 h1 = __float2bfloat16_rn(f1);
    float r0 = f0 - __bfloat162float(h0);
    float r1 = f1 - __bfloat162float(h1);
    unsigned short l0 = __bfloat16_as_ushort(__float2bfloat16_rn(r0));
    unsigned short l1 = __bfloat16_as_ushort(__float2bfloat16_rn(r1));
    lo = (unsigned)l0 | ((unsigned)l1 << 16);
    return (unsigned)__bfloat16_as_ushort(h0) | ((unsigned)__bfloat16_as_ushort(h1) << 16);
}

#define LDSM_X4(r, addr) \
  asm volatile("ldmatrix.sync.aligned.m8n8.x4.shared.b16 {%0,%1,%2,%3}, [%4];" \
    : "=r"((r)[0]), "=r"((r)[1]), "=r"((r)[2]), "=r"((r)[3]) : "r"(addr))
#define LDSM_X4_T(r, addr) \
  asm volatile("ldmatrix.sync.aligned.m8n8.x4.trans.shared.b16 {%0,%1,%2,%3}, [%4];" \
    : "=r"((r)[0]), "=r"((r)[1]), "=r"((r)[2]), "=r"((r)[3]) : "r"(addr))
#define MMA16816(d, a, b) \
  asm volatile("mma.sync.aligned.m16n8k16.row.col.f32.bf16.bf16.f32 " \
    "{%0,%1,%2,%3}, {%4,%5,%6,%7}, {%8,%9}, {%0,%1,%2,%3};" \
    : "+f"((d)[0]), "+f"((d)[1]), "+f"((d)[2]), "+f"((d)[3]) \
    : "r"((a)[0]), "r"((a)[1]), "r"((a)[2]), "r"((a)[3]), "r"((b)[0]), "r"((b)[1]))

// =================================================================
// bf16-split tensor-core GEMM: C[M,256] = A[M,256] * W[256,256]^T
// AMODE 0: A row-major [m][k].  AMODE 1: A stored transposed [k][t] (y1T)
// EPI 0: out transposed [b][n][t], +bias           (encode)
// EPI 1: out row-major, gelu(acc+bias)+skipT       (fc)
// EPI 2: out row-major, acc+bias                   (decode)
// Block tile 128(M) x 128(N), 8 warps (2x4), warp tile 64x32, K-chunk 32.
// =================================================================
template<int AMODE, int EPI>
__global__ __launch_bounds__(256)
void mma_gemm(const float* __restrict__ Aptr, const float* __restrict__ W,
              const float* __restrict__ bias, const float* __restrict__ skip,
              float* __restrict__ out)
{
    __shared__ unsigned short sAh[5120], sAl[5120], sWh[5120], sWl[5120];
    __shared__ float sbias[128];
    const int tid  = threadIdx.x;
    const int lane = tid & 31;
    const int wid  = tid >> 5;
    const int m0 = blockIdx.x * 128;
    const int n0 = blockIdx.y * 128;
    const int bb = m0 >> 13;
    const int t0 = m0 & (SEQL-1);
    const int wm = (wid >> 2) * 64;
    const int wn = (wid & 3) * 32;

    const uint32_t bAh = smem_to_u32(sAh);
    const uint32_t bAl = smem_to_u32(sAl);
    const uint32_t bWh = smem_to_u32(sWh);
    const uint32_t bWl = smem_to_u32(sWl);

    if (tid < 32) *(float4*)(sbias + tid*4) = *(const float4*)(bias + n0 + tid*4);

    float acc[16][4];
    #pragma unroll
    for (int i=0;i<16;i++){ acc[i][0]=0.f; acc[i][1]=0.f; acc[i][2]=0.f; acc[i][3]=0.f; }

    float4 pa[4], pw[4];
    // prefetch chunk 0
    #pragma unroll
    for (int i=0;i<4;i++){
        int idx = tid + i*256;
        if (AMODE==0){
            int r = idx>>3, c4 = (idx&7)<<2;
            pa[i] = *(const float4*)(Aptr + (size_t)(m0+r)*CHN + c4);
        } else {
            int kk = idx>>5, t4 = (idx&31)<<2;
            pa[i] = *(const float4*)(Aptr + ((size_t)(bb*CHN + kk))*SEQL + t0 + t4);
        }
        int r = idx>>3, c4 = (idx&7)<<2;
        pw[i] = *(const float4*)(W + (size_t)(n0+r)*CHN + c4);
    }

    for (int ch = 0; ch < 8; ch++){
        __syncthreads();
        // ---- convert + store to smem ----
        #pragma unroll
        for (int i=0;i<4;i++){
            int idx = tid + i*256;
            unsigned l0,l1;
            unsigned h0 = pk(pa[i].x, pa[i].y, l0);
            unsigned h1 = pk(pa[i].z, pa[i].w, l1);
            unsigned off;
            if (AMODE==0){ int r = idx>>3, c4 = (idx&7)<<2; off = r*40 + c4; }
            else         { int kk = idx>>5, t4 = (idx&31)<<2; off = kk*136 + t4; }
            *(uint2*)(sAh + off) = make_uint2(h0,h1);
            *(uint2*)(sAl + off) = make_uint2(l0,l1);
            h0 = pk(pw[i].x, pw[i].y, l0);
            h1 = pk(pw[i].z, pw[i].w, l1);
            int r = idx>>3, c4 = (idx&7)<<2;
            unsigned offw = r*40 + c4;
            *(uint2*)(sWh + offw) = make_uint2(h0,h1);
            *(uint2*)(sWl + offw) = make_uint2(l0,l1);
        }
        __syncthreads();
        // ---- prefetch next chunk ----
        if (ch < 7){
            int k0 = (ch+1)*32;
            #pragma unroll
            for (int i=0;i<4;i++){
                int idx = tid + i*256;
                if (AMODE==0){
                    int r = idx>>3, c4 = (idx&7)<<2;
                    pa[i] = *(const float4*)(Aptr + (size_t)(m0+r)*CHN + k0 + c4);
                } else {
                    int kk = idx>>5, t4 = (idx&31)<<2;
                    pa[i] = *(const float4*)(Aptr + ((size_t)(bb*CHN + k0 + kk))*SEQL + t0 + t4);
                }
                int r = idx>>3, c4 = (idx&7)<<2;
                pw[i] = *(const float4*)(W + (size_t)(n0+r)*CHN + k0 + c4);
            }
        }
        // ---- mma on current chunk: 2 k16 steps ----
        #pragma unroll
        for (int ks=0; ks<2; ks++){
            const int kh = ks*16;
            unsigned Ah[4][4], Al[4][4], Bh[4][2], Bl[4][2];
            #pragma unroll
            for (int mt=0; mt<4; mt++){
                unsigned off;
                if (AMODE==0){
                    int row = wm + mt*16 + (lane&15);
                    int col = kh + (lane>>4)*8;
                    off = (unsigned)(row*40 + col)*2;
                    LDSM_X4(Ah[mt], bAh + off);
                    LDSM_X4(Al[mt], bAl + off);
                } else {
                    int krow = kh + (lane&7) + ((lane>>4)&1)*8;
                    int col  = wm + mt*16 + ((lane>>3)&1)*8;
                    off = (unsigned)(krow*136 + col)*2;
                    LDSM_X4_T(Ah[mt], bAh + off);
                    LDSM_X4_T(Al[mt], bAl + off);
                }
            }
            #pragma unroll
            for (int np=0; np<2; np++){
                int row = wn + np*16 + (lane&7) + ((lane>>4)&1)*8;
                int col = kh + ((lane>>3)&1)*8;
                unsigned off = (unsigned)(row*40 + col)*2;
                unsigned r4[4];
                LDSM_X4(r4, bWh + off);
                Bh[np*2][0]=r4[0]; Bh[np*2][1]=r4[1]; Bh[np*2+1][0]=r4[2]; Bh[np*2+1][1]=r4[3];
                LDSM_X4(r4, bWl + off);
                Bl[np*2][0]=r4[0]; Bl[np*2][1]=r4[1]; Bl[np*2+1][0]=r4[2]; Bl[np*2+1][1]=r4[3];
            }
            #pragma unroll
            for (int mt=0; mt<4; mt++){
                #pragma unroll
                for (int nt=0; nt<4; nt++){
                    MMA16816(acc[mt*4+nt], Ah[mt], Bh[nt]);
                    MMA16816(acc[mt*4+nt], Ah[mt], Bl[nt]);
                    MMA16816(acc[mt*4+nt], Al[mt], Bh[nt]);
                }
            }
        }
    }

    // ---- epilogue ----
    const int grp = lane >> 2;
    const int qc  = (lane & 3) * 2;
    if (EPI == 0){
        #pragma unroll
        for (int mt=0; mt<4; mt++){
            int tA = t0 + wm + mt*16 + grp;
            #pragma unroll
            for (int nt=0; nt<4; nt++){
                int c  = wn + nt*8 + qc;           // local col
                float b0v = sbias[c], b1v = sbias[c+1];
                float* o0 = out + ((size_t)(bb*CHN + n0 + c))*SEQL;
                float* o1 = o0 + SEQL;
                float* a4 = acc[mt*4+nt];
                o0[tA]   = a4[0] + b0v;
                o1[tA]   = a4[1] + b1v;
                o0[tA+8] = a4[2] + b0v;
                o1[tA+8] = a4[3] + b1v;
            }
        }
    } else {
        #pragma unroll
        for (int mt=0; mt<4; mt++){
            int mg = m0 + wm + mt*16 + grp;
            int tA = mg & (SEQL-1);
            #pragma unroll
            for (int nt=0; nt<4; nt++){
                int c = wn + nt*8 + qc;
                float b0v = sbias[c], b1v = sbias[c+1];
                float* a4 = acc[mt*4+nt];
                float v0, v1, v2, v3;
                if (EPI == 1){
                    const float* sk = skip + ((size_t)(bb*CHN + n0 + c))*SEQL;
                    v0 = gelu_exact(a4[0] + b0v) + sk[tA];
                    v1 = gelu_exact(a4[1] + b1v) + sk[SEQL + tA];
                    v2 = gelu_exact(a4[2] + b0v) + sk[tA + 8];
                    v3 = gelu_exact(a4[3] + b1v) + sk[SEQL + tA + 8];
                } else {
                    v0 = a4[0] + b0v; v1 = a4[1] + b1v;
                    v2 = a4[2] + b0v; v3 = a4[3] + b1v;
                }
                *(float2*)(out + (size_t)mg*CHN + n0 + c)     = make_float2(v0, v1);
                *(float2*)(out + (size_t)(mg+8)*CHN + n0 + c) = make_float2(v2, v3);
            }
        }
    }
}

// ---------------- init ----------------
__global__ void init_kernel(){
    int i = blockIdx.x*blockDim.x + threadIdx.x;
    if (i < BSZ*CHN) g_mx_y[i] = 0u;
    if (i < NFFT){
        float th = -6.283185307179586f * (float)i / (float)NFFT;
        float s,c; sincosf(th,&s,&c);
        g_tw[i] = make_float2(c, s);
    }
}

// ---------------- kernel spectrum ----------------
__global__ void kf_kernel(const float* __restrict__ A, const float* __restrict__ Bp){
    int idx = blockIdx.x*blockDim.x + threadIdx.x;
    if (idx >= CHN*NFFT) return;
    int c = idx >> 10, k = idx & (NFFT-1);
    float th = -6.283185307179586f * (float)k / (float)NFFT;
    float sw, cw; sincosf(th, &sw, &cw);
    float wr = 1.f, wi = 0.f;
    float nr = 0.f, ni = 0.f, dr = 1.f, di = 0.f;
    const float* Ac = A  + c*ORD;
    const float* Bc = Bp + c*ORD;
    #pragma unroll 8
    for (int n = 0; n < ORD; n++){
        float bn = Bc[n];
        nr = fmaf(bn, wr, nr); ni = fmaf(bn, wi, ni);
        float wr2 = wr*cw - wi*sw;
        float wi2 = wr*sw + wi*cw;
        wr = wr2; wi = wi2;
        float an = Ac[n];
        dr = fmaf(an, wr, dr); di = fmaf(an, wi, di);
    }
    float inv = 1.f/(dr*dr + di*di);
    g_Kf[idx] = make_float2((nr*dr + ni*di)*inv, (ni*dr - nr*di)*inv);
}

// ---------------- radix-4 Stockham FFT, N=1024 ----------------
__device__ __forceinline__ void fft1024(float2* sb0, float2* sb1, const float2* stw, int tid){
    #pragma unroll
    for (int st=0; st<5; st++){
        const int s = 1 << (2*st);
        float2* src = (st & 1) ? sb1 : sb0;
        float2* dst = (st & 1) ? sb0 : sb1;
        int ps = tid & ~(s-1);
        float2 a = src[tid];
        float2 b = src[tid+256];
        float2 c = src[tid+512];
        float2 d = src[tid+768];
        float2 w1 = stw[ps];
        float2 w2 = stw[(2*ps) & (NFFT-1)];
        float2 w3 = stw[(3*ps) & (NFFT-1)];
        float2 apc = make_float2(a.x+c.x, a.y+c.y);
        float2 amc = make_float2(a.x-c.x, a.y-c.y);
        float2 bpd = make_float2(b.x+d.x, b.y+d.y);
        float2 bmd = make_float2(b.x-d.x, b.y-d.y);
        float2 jb  = make_float2(-bmd.y, bmd.x);
        int j0 = tid + 3*ps;
        dst[j0]       = make_float2(apc.x+bpd.x, apc.y+bpd.y);
        dst[j0+s]     = cmulf(w1, make_float2(amc.x-jb.x, amc.y-jb.y));
        dst[j0+2*s]   = cmulf(w2, make_float2(apc.x-bpd.x, apc.y-bpd.y));
        dst[j0+3*s]   = cmulf(w3, make_float2(amc.x+jb.x, amc.y+jb.y));
        __syncthreads();
    }
}

// ---------------- overlap-save FFT conv ----------------
__global__ __launch_bounds__(256)
void fftconv_kernel(const float* __restrict__ h0){
    __shared__ __align__(16) float2 sb0[NFFT];
    __shared__ __align__(16) float2 sb1[NFFT];
    __shared__ __align__(16) float2 stw[NFFT];
    __shared__ __align__(16) float2 skeep[HOP];
    const int chunk = blockIdx.x;
    const int cp    = blockIdx.y;
    const int b     = blockIdx.z;
    const int tid   = threadIdx.x;
    const int rowA  = (b*CHN + 2*cp) * SEQL;
    const int rowB  = rowA + SEQL;
    const int g0    = chunk*HOP - HOP;

    #pragma unroll
    for (int l=0;l<4;l++){
        int i = tid + l*256;
        stw[i] = g_tw[i];
        int t = g0 + i;
        float xa = 0.f, xb = 0.f;
        if (t >= 0){ xa = g_xeT[rowA + t]; xb = g_xeT[rowB + t]; }
        sb0[i] = make_float2(xa, xb);
        if (i >= HOP) skeep[i-HOP] = make_float2(xa, xb);
    }
    __syncthreads();

    fft1024(sb0, sb1, stw, tid);

    const int cbase0 = (2*cp)*NFFT;
    const int cbase1 = cbase0 + NFFT;
    #pragma unroll
    for (int l=0;l<4;l++){
        int k = tid + l*256;
        float2 Z  = sb1[k];
        float2 Zr = sb1[(NFFT - k) & (NFFT-1)];
        float2 Xa = make_float2(0.5f*(Z.x+Zr.x),  0.5f*(Z.y-Zr.y));
        float2 Xb = make_float2(0.5f*(Z.y+Zr.y), -0.5f*(Z.x-Zr.x));
        float2 Ka = g_Kf[cbase0 + k];
        float2 Kb = g_Kf[cbase1 + k];
        float2 Ya = cmulf(Xa, Ka);
        float2 Yb = cmulf(Xb, Kb);
        sb0[k] = make_float2(Ya.x - Yb.y, -(Ya.y + Yb.x));
    }
    __syncthreads();

    fft1024(sb0, sb1, stw, tid);

    const float h0v = h0[0];
    const float invN = 1.0f/(float)NFFT;
    #pragma unroll
    for (int l=0;l<2;l++){
        int i = HOP + tid + l*256;
        int t = g0 + i;
        float ha =  sb1[i].x * invN;
        float hb = -sb1[i].y * invN;
        float2 xv = skeep[i-HOP];
        g_y1T[rowA + t] = gelu_exact(ha + h0v*xv.x);
        g_y1T[rowB + t] = gelu_exact(hb + h0v*xv.y);
    }
}

// ---------------- LayerNorm (in-place on g_y2) ----------------
__global__ __launch_bounds__(256)
void ln_kernel(const float* __restrict__ gamma, const float* __restrict__ beta){
    int warp = threadIdx.x >> 5, lane = threadIdx.x & 31;
    int row = blockIdx.x*8 + warp;
    float* p = g_y2 + (size_t)row*CHN + lane*8;
    float4 v0 = *(float4*)p;
    float4 v1 = *(float4*)(p+4);
    float s  = v0.x+v0.y+v0.z+v0.w + v1.x+v1.y+v1.z+v1.w;
    float ss = v0.x*v0.x+v0.y*v0.y+v0.z*v0.z+v0.w*v0.w
             + v1.x*v1.x+v1.y*v1.y+v1.z*v1.z+v1.w*v1.w;
    #pragma unroll
    for (int o=16;o>0;o>>=1){
        s  += __shfl_xor_sync(0xffffffffu, s,  o);
        ss += __shfl_xor_sync(0xffffffffu, ss, o);
    }
    float mu  = s * (1.f/CHN);
    float var = ss * (1.f/CHN) - mu*mu;
    float r = rsqrtf(var + 1e-5f);
    float4 g0 = *(const float4*)(gamma + lane*8);
    float4 g1 = *(const float4*)(gamma + lane*8 + 4);
    float4 be0 = *(const float4*)(beta + lane*8);
    float4 be1 = *(const float4*)(beta + lane*8 + 4);
    v0.x = (v0.x-mu)*r*g0.x + be0.x;  v0.y = (v0.y-mu)*r*g0.y + be0.y;
    v0.z = (v0.z-mu)*r*g0.z + be0.z;  v0.w = (v0.w-mu)*r*g0.w + be0.w;
    v1.x = (v1.x-mu)*r*g1.x + be1.x;  v1.y = (v1.y-mu)*r*g1.y + be1.y;
    v1.z = (v1.z-mu)*r*g1.z + be1.z;  v1.w = (v1.w-mu)*r*g1.w + be1.w;
    *(float4*)p     = v0;
    *(float4*)(p+4) = v1;
}

// ---------------- max|xe| per (b,c) ----------------
__global__ __launch_bounds__(256)
void mxxe_kernel(){
    size_t base = (size_t)blockIdx.x * SEQL;
    float m = 0.f;
    for (int j = threadIdx.x*4; j < SEQL; j += 1024){
        float4 v = *(const float4*)(g_xeT + base + j);
        m = fmaxf(m, fmaxf(fmaxf(fabsf(v.x),fabsf(v.y)),fmaxf(fabsf(v.z),fabsf(v.w))));
    }
    __shared__ float sm[256];
    sm[threadIdx.x] = m; __syncthreads();
    for (int o=128;o>0;o>>=1){
        if (threadIdx.x<o) sm[threadIdx.x]=fmaxf(sm[threadIdx.x], sm[threadIdx.x+o]);
        __syncthreads();
    }
    if (threadIdx.x==0) g_mx_xe[blockIdx.x] = sm[0];
}

// ---------------- max|y| per (b,c) ----------------
__global__ __launch_bounds__(256)
void mxy_kernel(const float* __restrict__ y){
    int b   = blockIdx.x >> 5;
    int seg = blockIdx.x & 31;
    int c   = threadIdx.x;
    float m = 0.f;
    size_t base = ((size_t)b*SEQL + seg*256)*CHN + c;
    for (int t=0;t<256;t++) m = fmaxf(m, fabsf(y[base + (size_t)t*CHN]));
    atomicMax(&g_mx_y[b*CHN + c], __float_as_uint(m));
}

__global__ void hfinal_kernel(float* __restrict__ out){
    int i = blockIdx.x*blockDim.x + threadIdx.x;
    if (i < BSZ*CHN)
        out[i] = __uint_as_float(g_mx_y[i]) / (g_mx_xe[i] + 1e-6f);
}

// ---------------- launch ----------------
extern "C" void kernel_launch(void* const* d_in, const int* in_sizes, int n_in,
                              void* d_out, int out_size) {
    const float* x     = (const float*)d_in[0];
    const float* A     = (const float*)d_in[1];
    const float* Bp    = (const float*)d_in[2];
    const float* h0    = (const float*)d_in[3];
    const float* W_enc = (const float*)d_in[4];
    const float* b_enc = (const float*)d_in[5];
    const float* W_fc  = (const float*)d_in[6];
    const float* b_fc  = (const float*)d_in[7];
    const float* gamma = (const float*)d_in[8];
    const float* beta  = (const float*)d_in[9];
    const float* W_dec = (const float*)d_in[10];
    const float* b_dec = (const float*)d_in[11];
    float* out = (float*)d_out;

    float *p_xeT, *p_y1T, *p_y2;
    cudaGetSymbolAddress((void**)&p_xeT, g_xeT);
    cudaGetSymbolAddress((void**)&p_y1T, g_y1T);
    cudaGetSymbolAddress((void**)&p_y2,  g_y2);

    init_kernel<<<8, 256>>>();
    kf_kernel<<<(CHN*NFFT)/256, 256>>>(A, Bp);

    dim3 gg(MTOT/128, CHN/128);
    // encode: xeT = (x @ W_enc^T + b_enc), transposed layout
    mma_gemm<0,0><<<gg, 256>>>(x, W_enc, b_enc, nullptr, p_xeT);
    mxxe_kernel<<<BSZ*CHN, 256>>>();
    // FFT long conv + gelu -> y1T
    fftconv_kernel<<<dim3(NCHUNK, CHN/2, BSZ), 256>>>(h0);
    // fc: y2 = gelu(y1 @ W_fc^T + b_fc) + xe, row-major (A read transposed via ldmatrix.trans)
    mma_gemm<1,1><<<gg, 256>>>(p_y1T, W_fc, b_fc, p_xeT, p_y2);
    // LayerNorm in-place
    ln_kernel<<<MTOT/8, 256>>>(gamma, beta);
    // decode: y = y2n @ W_dec^T + b_dec -> d_out
    mma_gemm<0,2><<<gg, 256>>>(p_y2, W_dec, b_dec, nullptr, out);
    // h = max|y| / (max|xe| + eps)
    mxy_kernel<<<BSZ*32, 256>>>(out);
    hfinal_kernel<<<8, 256>>>(out + NELEM);
}

// round 8
// speedup vs baseline: 1.8848x; 1.2172x over previous
#include <cuda_runtime.h>
#include <cuda_bf16.h>
#include <math.h>
#include <stdint.h>

#define BSZ   8
#define SEQL  8192
#define CHN   256
#define ORD   64
#define NFFT  1024
#define HOP   512
#define NCHUNK 16
#define MTOT  (BSZ*SEQL)          // 65536
#define NELEM (BSZ*SEQL*CHN)      // 16777216

// ---------------- device scratch ----------------
__device__ float  g_xeT[NELEM];       // [b][c][t]
__device__ float  g_y1T[NELEM];       // [b][c][t]
__device__ float  g_y2[NELEM];        // [b][t][c]
__device__ float2 g_Kf[CHN*NFFT];
__device__ float2 g_tw[NFFT];
__device__ unsigned int g_mx_xe[BSZ*CHN];
__device__ unsigned int g_mx_y[BSZ*CHN];
__device__ unsigned short g_Wh[3*CHN*CHN];   // bf16 hi bits, 3 weight mats
__device__ unsigned short g_Wl[3*CHN*CHN];   // bf16 lo bits

__device__ __forceinline__ float2 cmulf(float2 a, float2 b){
    return make_float2(fmaf(a.x,b.x,-a.y*b.y), fmaf(a.x,b.y,a.y*b.x));
}
__device__ __forceinline__ float gelu_exact(float v){
    return 0.5f*v*(1.0f+erff(v*0.70710678118654752f));
}
__device__ __forceinline__ uint32_t smem_to_u32(const void* p){
    uint32_t a;
    asm("{ .reg .u64 t; cvta.to.shared.u64 t, %1; cvt.u32.u64 %0, t; }" : "=r"(a) : "l"(p));
    return a;
}

// bf16 hi/lo split packer: returns hi-pair, writes lo-pair
__device__ __forceinline__ unsigned pk(float f0, float f1, unsigned &lo){
    __nv_bfloat16 h0 = __float2bfloat16_rn(f0);
    __nv_bfloat16 h1 = __float2bfloat16_rn(f1);
    float r0 = f0 - __bfloat162float(h0);
    float r1 = f1 - __bfloat162float(h1);
    unsigned short l0 = __bfloat16_as_ushort(__float2bfloat16_rn(r0));
    unsigned short l1 = __bfloat16_as_ushort(__float2bfloat16_rn(r1));
    lo = (unsigned)l0 | ((unsigned)l1 << 16);
    return (unsigned)__bfloat16_as_ushort(h0) | ((unsigned)__bfloat16_as_ushort(h1) << 16);
}

#define LDSM_X4(r, addr) \
  asm volatile("ldmatrix.sync.aligned.m8n8.x4.shared.b16 {%0,%1,%2,%3}, [%4];" \
    : "=r"((r)[0]), "=r"((r)[1]), "=r"((r)[2]), "=r"((r)[3]) : "r"(addr))
#define LDSM_X4_T(r, addr) \
  asm volatile("ldmatrix.sync.aligned.m8n8.x4.trans.shared.b16 {%0,%1,%2,%3}, [%4];" \
    : "=r"((r)[0]), "=r"((r)[1]), "=r"((r)[2]), "=r"((r)[3]) : "r"(addr))
#define MMA16816(d, a, b) \
  asm volatile("mma.sync.aligned.m16n8k16.row.col.f32.bf16.bf16.f32 " \
    "{%0,%1,%2,%3}, {%4,%5,%6,%7}, {%8,%9}, {%0,%1,%2,%3};" \
    : "+f"((d)[0]), "+f"((d)[1]), "+f"((d)[2]), "+f"((d)[3]) \
    : "r"((a)[0]), "r"((a)[1]), "r"((a)[2]), "r"((a)[3]), "r"((b)[0]), "r"((b)[1]))
#define CP_ASYNC16(dst, src) \
  asm volatile("cp.async.cg.shared.global [%0], [%1], 16;" :: "r"(dst), "l"(src))
#define CP_COMMIT  asm volatile("cp.async.commit_group;" ::: "memory")
#define CP_WAIT0   asm volatile("cp.async.wait_group 0;" ::: "memory")

// dynamic smem layout (bytes); per-region double buffers of 10240B
#define OFF_WH   0
#define OFF_WL   20480
#define OFF_AH   40960
#define OFF_AL   61440
#define OFF_BIAS 81920
#define SMEM_GEMM (81920 + 512)

// =================================================================
// bf16-split tensor-core GEMM: C[M,256] = A[M,256] * W[256,256]^T
// W given preconverted as bf16 hi/lo (row-major [n][k]).
// AMODE 0: A row-major [m][k].  AMODE 1: A stored transposed [k][t] (y1T)
// EPI 0: out transposed [b][n][t], +bias, fused max|v| -> g_mx_xe  (encode)
// EPI 1: out row-major, gelu(acc+bias)+skipT                      (fc)
// EPI 2: out row-major, acc+bias, fused max|v| -> g_mx_y          (decode)
// Block tile 128(M) x 128(N), 8 warps (2x4), warp tile 64x32, K-chunk 32.
// =================================================================
template<int AMODE, int EPI>
__global__ __launch_bounds__(256)
void mma_gemm(const float* __restrict__ Aptr,
              const unsigned short* __restrict__ Wh,
              const unsigned short* __restrict__ Wl,
              const float* __restrict__ bias, const float* __restrict__ skip,
              float* __restrict__ out)
{
    extern __shared__ __align__(128) char smem[];
    const uint32_t sbase = smem_to_u32(smem);
    float* sbias = (float*)(smem + OFF_BIAS);
    const int tid  = threadIdx.x;
    const int lane = tid & 31;
    const int wid  = tid >> 5;
    const int m0 = blockIdx.x * 128;
    const int n0 = blockIdx.y * 128;
    const int bb = m0 >> 13;
    const int t0 = m0 & (SEQL-1);
    const int wm = (wid >> 2) * 64;
    const int wn = (wid & 3) * 32;

    if (tid < 32) *(float4*)(sbias + tid*4) = *(const float4*)(bias + n0 + tid*4);

    float acc[16][4];
    #pragma unroll
    for (int i=0;i<16;i++){ acc[i][0]=0.f; acc[i][1]=0.f; acc[i][2]=0.f; acc[i][3]=0.f; }

    // W cp.async for one chunk into buffer bu
    auto cpW = [&](int k0, int bu){
        #pragma unroll
        for (int i=0;i<2;i++){
            int idx = tid + i*256;              // 0..511
            int row = idx >> 2, c16 = idx & 3;
            uint32_t doff = (uint32_t)(row*80 + c16*16) + (uint32_t)(bu*10240);
            size_t  soff = (size_t)(n0+row)*CHN + k0 + c16*8;
            CP_ASYNC16(sbase + OFF_WH + doff, (const void*)(Wh + soff));
            CP_ASYNC16(sbase + OFF_WL + doff, (const void*)(Wl + soff));
        }
    };
    // A global loads for one chunk
    float4 pa[4];
    auto ldA = [&](int k0){
        #pragma unroll
        for (int i=0;i<4;i++){
            int idx = tid + i*256;
            if (AMODE==0){
                int r = idx>>3, c4 = (idx&7)<<2;
                pa[i] = *(const float4*)(Aptr + (size_t)(m0+r)*CHN + k0 + c4);
            } else {
                int kk = idx>>5, t4 = (idx&31)<<2;
                pa[i] = *(const float4*)(Aptr + ((size_t)(bb*CHN + k0 + kk))*SEQL + t0 + t4);
            }
        }
    };
    // convert + store A regs into buffer bu
    auto stA = [&](int bu){
        uint32_t base = (uint32_t)(bu*10240);
        #pragma unroll
        for (int i=0;i<4;i++){
            int idx = tid + i*256;
            unsigned l0,l1;
            unsigned h0 = pk(pa[i].x, pa[i].y, l0);
            unsigned h1 = pk(pa[i].z, pa[i].w, l1);
            unsigned off;
            if (AMODE==0){ int r = idx>>3, c4 = (idx&7)<<2; off = (r*40 + c4)*2; }
            else         { int kk = idx>>5, t4 = (idx&31)<<2; off = (kk*136 + t4)*2; }
            *(uint2*)(smem + OFF_AH + base + off) = make_uint2(h0,h1);
            *(uint2*)(smem + OFF_AL + base + off) = make_uint2(l0,l1);
        }
    };

    // prologue: chunk 0 -> buffer 0
    cpW(0, 0); CP_COMMIT;
    ldA(0);
    stA(0);
    CP_WAIT0;
    __syncthreads();

    for (int ch = 0; ch < 8; ch++){
        const int cur = ch & 1, nxt = cur ^ 1;
        if (ch < 7){
            cpW((ch+1)*32, nxt); CP_COMMIT;
            ldA((ch+1)*32);
        }
        const uint32_t bAh = sbase + OFF_AH + cur*10240;
        const uint32_t bAl = sbase + OFF_AL + cur*10240;
        const uint32_t bWh = sbase + OFF_WH + cur*10240;
        const uint32_t bWl = sbase + OFF_WL + cur*10240;
        #pragma unroll
        for (int ks=0; ks<2; ks++){
            const int kh = ks*16;
            unsigned Ah[4][4], Al[4][4], Bh[4][2], Bl[4][2];
            #pragma unroll
            for (int mt=0; mt<4; mt++){
                unsigned off;
                if (AMODE==0){
                    int row = wm + mt*16 + (lane&15);
                    int col = kh + (lane>>4)*8;
                    off = (unsigned)(row*40 + col)*2;
                    LDSM_X4(Ah[mt], bAh + off);
                    LDSM_X4(Al[mt], bAl + off);
                } else {
                    int krow = kh + (lane&7) + ((lane>>4)&1)*8;
                    int col  = wm + mt*16 + ((lane>>3)&1)*8;
                    off = (unsigned)(krow*136 + col)*2;
                    LDSM_X4_T(Ah[mt], bAh + off);
                    LDSM_X4_T(Al[mt], bAl + off);
                }
            }
            #pragma unroll
            for (int np=0; np<2; np++){
                int row = wn + np*16 + (lane&7) + ((lane>>4)&1)*8;
                int col = kh + ((lane>>3)&1)*8;
                unsigned off = (unsigned)(row*40 + col)*2;
                unsigned r4[4];
                LDSM_X4(r4, bWh + off);
                Bh[np*2][0]=r4[0]; Bh[np*2][1]=r4[1]; Bh[np*2+1][0]=r4[2]; Bh[np*2+1][1]=r4[3];
                LDSM_X4(r4, bWl + off);
                Bl[np*2][0]=r4[0]; Bl[np*2][1]=r4[1]; Bl[np*2+1][0]=r4[2]; Bl[np*2+1][1]=r4[3];
            }
            #pragma unroll
            for (int mt=0; mt<4; mt++){
                #pragma unroll
                for (int nt=0; nt<4; nt++){
                    MMA16816(acc[mt*4+nt], Ah[mt], Bh[nt]);
                    MMA16816(acc[mt*4+nt], Ah[mt], Bl[nt]);
                    MMA16816(acc[mt*4+nt], Al[mt], Bh[nt]);
                }
            }
        }
        if (ch < 7){
            stA(nxt);
            CP_WAIT0;
        }
        __syncthreads();
    }

    // ---- epilogue ----
    const int grp = lane >> 2;
    const int qc  = (lane & 3) * 2;
    float chmax[8];
    #pragma unroll
    for (int i=0;i<8;i++) chmax[i]=0.f;

    if (EPI == 0){
        #pragma unroll
        for (int mt=0; mt<4; mt++){
            int tA = t0 + wm + mt*16 + grp;
            #pragma unroll
            for (int nt=0; nt<4; nt++){
                int c  = wn + nt*8 + qc;
                float b0v = sbias[c], b1v = sbias[c+1];
                float* o0 = out + ((size_t)(bb*CHN + n0 + c))*SEQL;
                float* o1 = o0 + SEQL;
                float* a4 = acc[mt*4+nt];
                float v0 = a4[0] + b0v, v1 = a4[1] + b1v;
                float v2 = a4[2] + b0v, v3 = a4[3] + b1v;
                o0[tA]   = v0;  o1[tA]   = v1;
                o0[tA+8] = v2;  o1[tA+8] = v3;
                chmax[nt*2]   = fmaxf(chmax[nt*2],   fmaxf(fabsf(v0), fabsf(v2)));
                chmax[nt*2+1] = fmaxf(chmax[nt*2+1], fmaxf(fabsf(v1), fabsf(v3)));
            }
        }
    } else {
        #pragma unroll
        for (int mt=0; mt<4; mt++){
            int mg = m0 + wm + mt*16 + grp;
            int tA = mg & (SEQL-1);
            #pragma unroll
            for (int nt=0; nt<4; nt++){
                int c = wn + nt*8 + qc;
                float b0v = sbias[c], b1v = sbias[c+1];
                float* a4 = acc[mt*4+nt];
                float v0, v1, v2, v3;
                if (EPI == 1){
                    const float* sk = skip + ((size_t)(bb*CHN + n0 + c))*SEQL;
                    v0 = gelu_exact(a4[0] + b0v) + sk[tA];
                    v1 = gelu_exact(a4[1] + b1v) + sk[SEQL + tA];
                    v2 = gelu_exact(a4[2] + b0v) + sk[tA + 8];
                    v3 = gelu_exact(a4[3] + b1v) + sk[SEQL + tA + 8];
                } else {
                    v0 = a4[0] + b0v; v1 = a4[1] + b1v;
                    v2 = a4[2] + b0v; v3 = a4[3] + b1v;
                    chmax[nt*2]   = fmaxf(chmax[nt*2],   fmaxf(fabsf(v0), fabsf(v2)));
                    chmax[nt*2+1] = fmaxf(chmax[nt*2+1], fmaxf(fabsf(v1), fabsf(v3)));
                }
                *(float2*)(out + (size_t)mg*CHN + n0 + c)     = make_float2(v0, v1);
                *(float2*)(out + (size_t)(mg+8)*CHN + n0 + c) = make_float2(v2, v3);
            }
        }
    }
    if (EPI == 0 || EPI == 2){
        #pragma unroll
        for (int j=0;j<8;j++){
            chmax[j] = fmaxf(chmax[j], __shfl_xor_sync(0xffffffffu, chmax[j], 4));
            chmax[j] = fmaxf(chmax[j], __shfl_xor_sync(0xffffffffu, chmax[j], 8));
            chmax[j] = fmaxf(chmax[j], __shfl_xor_sync(0xffffffffu, chmax[j], 16));
        }
        if (lane < 4){
            unsigned int* dst = (EPI==0) ? g_mx_xe : g_mx_y;
            #pragma unroll
            for (int nt=0; nt<4; nt++){
                int c0 = n0 + wn + nt*8 + lane*2;
                atomicMax(&dst[bb*CHN + c0],     __float_as_uint(chmax[nt*2]));
                atomicMax(&dst[bb*CHN + c0 + 1], __float_as_uint(chmax[nt*2+1]));
            }
        }
    }
}

// ---------------- weight preconvert: fp32 -> bf16 hi/lo ----------------
__global__ void wconv_kernel(const float* __restrict__ We,
                             const float* __restrict__ Wf,
                             const float* __restrict__ Wd){
    int i = blockIdx.x*256 + threadIdx.x;      // 0 .. 3*65536-1
    const float* src = (i < CHN*CHN) ? We : ((i < 2*CHN*CHN) ? Wf : Wd);
    float v = src[i & (CHN*CHN-1)];
    __nv_bfloat16 h = __float2bfloat16_rn(v);
    float r = v - __bfloat162float(h);
    g_Wh[i] = __bfloat16_as_ushort(h);
    g_Wl[i] = __bfloat16_as_ushort(__float2bfloat16_rn(r));
}

// ---------------- init ----------------
__global__ void init_kernel(){
    int i = blockIdx.x*blockDim.x + threadIdx.x;
    if (i < BSZ*CHN){ g_mx_y[i] = 0u; g_mx_xe[i] = 0u; }
    if (i < NFFT){
        float th = -6.283185307179586f * (float)i / (float)NFFT;
        float s,c; sincosf(th,&s,&c);
        g_tw[i] = make_float2(c, s);
    }
}

// ---------------- kernel spectrum ----------------
__global__ void kf_kernel(const float* __restrict__ A, const float* __restrict__ Bp){
    int idx = blockIdx.x*blockDim.x + threadIdx.x;
    if (idx >= CHN*NFFT) return;
    int c = idx >> 10, k = idx & (NFFT-1);
    float th = -6.283185307179586f * (float)k / (float)NFFT;
    float sw, cw; sincosf(th, &sw, &cw);
    float wr = 1.f, wi = 0.f;
    float nr = 0.f, ni = 0.f, dr = 1.f, di = 0.f;
    const float* Ac = A  + c*ORD;
    const float* Bc = Bp + c*ORD;
    #pragma unroll 8
    for (int n = 0; n < ORD; n++){
        float bn = Bc[n];
        nr = fmaf(bn, wr, nr); ni = fmaf(bn, wi, ni);
        float wr2 = wr*cw - wi*sw;
        float wi2 = wr*sw + wi*cw;
        wr = wr2; wi = wi2;
        float an = Ac[n];
        dr = fmaf(an, wr, dr); di = fmaf(an, wi, di);
    }
    float inv = 1.f/(dr*dr + di*di);
    g_Kf[idx] = make_float2((nr*dr + ni*di)*inv, (ni*dr - nr*di)*inv);
}

// ---------------- radix-4 Stockham FFT, N=1024 ----------------
__device__ __forceinline__ void fft1024(float2* sb0, float2* sb1, const float2* stw, int tid){
    #pragma unroll
    for (int st=0; st<5; st++){
        const int s = 1 << (2*st);
        float2* src = (st & 1) ? sb1 : sb0;
        float2* dst = (st & 1) ? sb0 : sb1;
        int ps = tid & ~(s-1);
        float2 a = src[tid];
        float2 b = src[tid+256];
        float2 c = src[tid+512];
        float2 d = src[tid+768];
        float2 w1 = stw[ps];
        float2 w2 = stw[(2*ps) & (NFFT-1)];
        float2 w3 = stw[(3*ps) & (NFFT-1)];
        float2 apc = make_float2(a.x+c.x, a.y+c.y);
        float2 amc = make_float2(a.x-c.x, a.y-c.y);
        float2 bpd = make_float2(b.x+d.x, b.y+d.y);
        float2 bmd = make_float2(b.x-d.x, b.y-d.y);
        float2 jb  = make_float2(-bmd.y, bmd.x);
        int j0 = tid + 3*ps;
        dst[j0]       = make_float2(apc.x+bpd.x, apc.y+bpd.y);
        dst[j0+s]     = cmulf(w1, make_float2(amc.x-jb.x, amc.y-jb.y));
        dst[j0+2*s]   = cmulf(w2, make_float2(apc.x-bpd.x, apc.y-bpd.y));
        dst[j0+3*s]   = cmulf(w3, make_float2(amc.x+jb.x, amc.y+jb.y));
        __syncthreads();
    }
}

// ---------------- overlap-save FFT conv ----------------
__global__ __launch_bounds__(256)
void fftconv_kernel(const float* __restrict__ h0){
    __shared__ __align__(16) float2 sb0[NFFT];
    __shared__ __align__(16) float2 sb1[NFFT];
    __shared__ __align__(16) float2 stw[NFFT];
    __shared__ __align__(16) float2 skeep[HOP];
    const int chunk = blockIdx.x;
    const int cp    = blockIdx.y;
    const int b     = blockIdx.z;
    const int tid   = threadIdx.x;
    const int rowA  = (b*CHN + 2*cp) * SEQL;
    const int rowB  = rowA + SEQL;
    const int g0    = chunk*HOP - HOP;

    #pragma unroll
    for (int l=0;l<4;l++){
        int i = tid + l*256;
        stw[i] = g_tw[i];
        int t = g0 + i;
        float xa = 0.f, xb = 0.f;
        if (t >= 0){ xa = g_xeT[rowA + t]; xb = g_xeT[rowB + t]; }
        sb0[i] = make_float2(xa, xb);
        if (i >= HOP) skeep[i-HOP] = make_float2(xa, xb);
    }
    __syncthreads();

    fft1024(sb0, sb1, stw, tid);

    const int cbase0 = (2*cp)*NFFT;
    const int cbase1 = cbase0 + NFFT;
    #pragma unroll
    for (int l=0;l<4;l++){
        int k = tid + l*256;
        float2 Z  = sb1[k];
        float2 Zr = sb1[(NFFT - k) & (NFFT-1)];
        float2 Xa = make_float2(0.5f*(Z.x+Zr.x),  0.5f*(Z.y-Zr.y));
        float2 Xb = make_float2(0.5f*(Z.y+Zr.y), -0.5f*(Z.x-Zr.x));
        float2 Ka = g_Kf[cbase0 + k];
        float2 Kb = g_Kf[cbase1 + k];
        float2 Ya = cmulf(Xa, Ka);
        float2 Yb = cmulf(Xb, Kb);
        sb0[k] = make_float2(Ya.x - Yb.y, -(Ya.y + Yb.x));
    }
    __syncthreads();

    fft1024(sb0, sb1, stw, tid);

    const float h0v = h0[0];
    const float invN = 1.0f/(float)NFFT;
    #pragma unroll
    for (int l=0;l<2;l++){
        int i = HOP + tid + l*256;
        int t = g0 + i;
        float ha =  sb1[i].x * invN;
        float hb = -sb1[i].y * invN;
        float2 xv = skeep[i-HOP];
        g_y1T[rowA + t] = gelu_exact(ha + h0v*xv.x);
        g_y1T[rowB + t] = gelu_exact(hb + h0v*xv.y);
    }
}

// ---------------- LayerNorm (in-place on g_y2) ----------------
__global__ __launch_bounds__(256)
void ln_kernel(const float* __restrict__ gamma, const float* __restrict__ beta){
    int warp = threadIdx.x >> 5, lane = threadIdx.x & 31;
    int row = blockIdx.x*8 + warp;
    float* p = g_y2 + (size_t)row*CHN + lane*8;
    float4 v0 = *(float4*)p;
    float4 v1 = *(float4*)(p+4);
    float s  = v0.x+v0.y+v0.z+v0.w + v1.x+v1.y+v1.z+v1.w;
    float ss = v0.x*v0.x+v0.y*v0.y+v0.z*v0.z+v0.w*v0.w
             + v1.x*v1.x+v1.y*v1.y+v1.z*v1.z+v1.w*v1.w;
    #pragma unroll
    for (int o=16;o>0;o>>=1){
        s  += __shfl_xor_sync(0xffffffffu, s,  o);
        ss += __shfl_xor_sync(0xffffffffu, ss, o);
    }
    float mu  = s * (1.f/CHN);
    float var = ss * (1.f/CHN) - mu*mu;
    float r = rsqrtf(var + 1e-5f);
    float4 g0 = *(const float4*)(gamma + lane*8);
    float4 g1 = *(const float4*)(gamma + lane*8 + 4);
    float4 be0 = *(const float4*)(beta + lane*8);
    float4 be1 = *(const float4*)(beta + lane*8 + 4);
    v0.x = (v0.x-mu)*r*g0.x + be0.x;  v0.y = (v0.y-mu)*r*g0.y + be0.y;
    v0.z = (v0.z-mu)*r*g0.z + be0.z;  v0.w = (v0.w-mu)*r*g0.w + be0.w;
    v1.x = (v1.x-mu)*r*g1.x + be1.x;  v1.y = (v1.y-mu)*r*g1.y + be1.y;
    v1.z = (v1.z-mu)*r*g1.z + be1.z;  v1.w = (v1.w-mu)*r*g1.w + be1.w;
    *(float4*)p     = v0;
    *(float4*)(p+4) = v1;
}

__global__ void hfinal_kernel(float* __restrict__ out){
    int i = blockIdx.x*blockDim.x + threadIdx.x;
    if (i < BSZ*CHN)
        out[i] = __uint_as_float(g_mx_y[i]) / (__uint_as_float(g_mx_xe[i]) + 1e-6f);
}

// ---------------- launch ----------------
extern "C" void kernel_launch(void* const* d_in, const int* in_sizes, int n_in,
                              void* d_out, int out_size) {
    const float* x     = (const float*)d_in[0];
    const float* A     = (const float*)d_in[1];
    const float* Bp    = (const float*)d_in[2];
    const float* h0    = (const float*)d_in[3];
    const float* W_enc = (const float*)d_in[4];
    const float* b_enc = (const float*)d_in[5];
    const float* W_fc  = (const float*)d_in[6];
    const float* b_fc  = (const float*)d_in[7];
    const float* gamma = (const float*)d_in[8];
    const float* beta  = (const float*)d_in[9];
    const float* W_dec = (const float*)d_in[10];
    const float* b_dec = (const float*)d_in[11];
    float* out = (float*)d_out;

    float *p_xeT, *p_y1T, *p_y2;
    unsigned short *p_Wh, *p_Wl;
    cudaGetSymbolAddress((void**)&p_xeT, g_xeT);
    cudaGetSymbolAddress((void**)&p_y1T, g_y1T);
    cudaGetSymbolAddress((void**)&p_y2,  g_y2);
    cudaGetSymbolAddress((void**)&p_Wh,  g_Wh);
    cudaGetSymbolAddress((void**)&p_Wl,  g_Wl);

    cudaFuncSetAttribute(mma_gemm<0,0>, cudaFuncAttributeMaxDynamicSharedMemorySize, SMEM_GEMM);
    cudaFuncSetAttribute(mma_gemm<1,1>, cudaFuncAttributeMaxDynamicSharedMemorySize, SMEM_GEMM);
    cudaFuncSetAttribute(mma_gemm<0,2>, cudaFuncAttributeMaxDynamicSharedMemorySize, SMEM_GEMM);

    init_kernel<<<8, 256>>>();
    kf_kernel<<<(CHN*NFFT)/256, 256>>>(A, Bp);
    wconv_kernel<<<3*CHN*CHN/256, 256>>>(W_enc, W_fc, W_dec);

    dim3 gg(MTOT/128, CHN/128);
    // encode: xeT = (x @ W_enc^T + b_enc), transposed layout, fused max|xe|
    mma_gemm<0,0><<<gg, 256, SMEM_GEMM>>>(x, p_Wh, p_Wl, b_enc, nullptr, p_xeT);
    // FFT long conv + gelu -> y1T
    fftconv_kernel<<<dim3(NCHUNK, CHN/2, BSZ), 256>>>(h0);
    // fc: y2 = gelu(y1 @ W_fc^T + b_fc) + xe
    mma_gemm<1,1><<<gg, 256, SMEM_GEMM>>>(p_y1T, p_Wh + CHN*CHN, p_Wl + CHN*CHN, b_fc, p_xeT, p_y2);
    // LayerNorm in-place
    ln_kernel<<<MTOT/8, 256>>>(gamma, beta);
    // decode: y = y2n @ W_dec^T + b_dec -> d_out, fused max|y|
    mma_gemm<0,2><<<gg, 256, SMEM_GEMM>>>(p_y2, p_Wh + 2*CHN*CHN, p_Wl + 2*CHN*CHN, b_dec, nullptr, out);
    // h = max|y| / (max|xe| + eps)
    hfinal_kernel<<<8, 256>>>(out + NELEM);
}